// round 13
// baseline (speedup 1.0000x reference)
#include <cuda_runtime.h>
#include <cuda_bf16.h>

// out = x + total, total = n*(n-1)/2 if n>1 else 0, n = trunc(sum(x)),
// x: 8192x8192 fp32 (64M elems, 256MB).
//
// R12 post-mortem applied:
//  - explicit PDL triggers reverted (neutral/negative).
//  - reduce reshaped to the add's proven geometry: non-persistent,
//    16384 blocks x 256 thr x 4 front-batched float4, contiguous 16KB
//    window per block. Block->chunk mapping REVERSED so x's front is read
//    last (L2 carryover for the add is measurably worth ~5us).
//  - add unchanged (74.3us @ 6.47 TB/s DRAM): 4 float4/thread, __ldcs
//    prelude before cudaGridDependencySynchronize(), __stcs stores.

#define NTHREADS 256
#define RED_BLOCKS 16384    // n4 / (256*4)

__device__ double g_partials[RED_BLOCKS];
__device__ float g_total;
__device__ unsigned int g_arrive;   // zero-init; finisher resets each launch

__global__ __launch_bounds__(NTHREADS)
void reduce_kernel(const float4* __restrict__ x4, long long n4) {
    // reversed chunk mapping: first-scheduled blocks eat the tail of x,
    // so L2 ends holding x's front (what the add reads first).
    const int cb = (RED_BLOCKS - 1) - (int)blockIdx.x;
    const long long base = (long long)cb * (4 * NTHREADS) + threadIdx.x;
    const long long i0 = base;
    const long long i1 = base + NTHREADS;
    const long long i2 = base + 2 * NTHREADS;
    const long long i3 = base + 3 * NTHREADS;

    float a0 = 0.f, a1 = 0.f, a2 = 0.f, a3 = 0.f;
    if (i0 < n4) { float4 v = x4[i0]; a0 += v.x; a1 += v.y; a2 += v.z; a3 += v.w; }
    if (i1 < n4) { float4 v = x4[i1]; a0 += v.x; a1 += v.y; a2 += v.z; a3 += v.w; }
    if (i2 < n4) { float4 v = x4[i2]; a0 += v.x; a1 += v.y; a2 += v.z; a3 += v.w; }
    if (i3 < n4) { float4 v = x4[i3]; a0 += v.x; a1 += v.y; a2 += v.z; a3 += v.w; }

    double acc = ((double)a0 + (double)a1) + ((double)a2 + (double)a3);

    // warp reduce (double shuffles), then cross-warp via smem
    #pragma unroll
    for (int off = 16; off > 0; off >>= 1)
        acc += __shfl_down_sync(0xFFFFFFFFu, acc, off);

    __shared__ double sw[NTHREADS / 32];
    const int lane = threadIdx.x & 31;
    const int warp = threadIdx.x >> 5;
    if (lane == 0) sw[warp] = acc;
    __syncthreads();
    if (warp == 0) {
        double a = (lane < NTHREADS / 32) ? sw[lane] : 0.0;
        #pragma unroll
        for (int off = 4; off > 0; off >>= 1)
            a += __shfl_down_sync(0xFFFFFFFFu, a, off);
        if (lane == 0) sw[0] = a;
    }
    __syncthreads();

    __shared__ int is_last;
    if (threadIdx.x == 0) {
        g_partials[cb] = sw[0];               // indexed by chunk: fixed order
        __threadfence();                      // partial visible GPU-wide
        unsigned int prev = atomicAdd(&g_arrive, 1u);
        is_last = (prev == RED_BLOCKS - 1);
        if (is_last) atomicExch(&g_arrive, 0u);  // reset for next graph replay
    }
    __syncthreads();

    // Last-arriving CTA finalizes in a FIXED order -> deterministic result
    // regardless of which CTA is last.
    if (is_last) {
        __shared__ double s[NTHREADS];
        double acc2 = 0.0;
        #pragma unroll 8
        for (int i = threadIdx.x; i < RED_BLOCKS; i += NTHREADS)
            acc2 += g_partials[i];
        s[threadIdx.x] = acc2;
        __syncthreads();
        #pragma unroll
        for (int off = NTHREADS / 2; off > 0; off >>= 1) {
            if (threadIdx.x < off) s[threadIdx.x] += s[threadIdx.x + off];
            __syncthreads();
        }
        if (threadIdx.x == 0) {
            double total_sum = s[0];
            double nn = trunc(total_sum);   // int() truncates toward zero
            g_total = (float)((nn > 1.0) ? nn * (nn - 1.0) * 0.5 : 0.0);
        }
    }
}

// Non-persistent streaming add, 4 float4/thread, PDL-overlapped:
// all loads issue before the grid-dependency sync (read-only, no hazard),
// g_total is read after it.
__global__ __launch_bounds__(NTHREADS)
void add_kernel(const float4* __restrict__ x4, float4* __restrict__ o4,
                long long n4) {
    const long long base = (long long)blockIdx.x * (4 * NTHREADS) + threadIdx.x;
    const long long i0 = base;
    const long long i1 = base + NTHREADS;
    const long long i2 = base + 2 * NTHREADS;
    const long long i3 = base + 3 * NTHREADS;

    float4 v0, v1, v2, v3;
    bool p0 = i0 < n4, p1 = i1 < n4, p2 = i2 < n4, p3 = i3 < n4;
    if (p0) v0 = __ldcs(&x4[i0]);
    if (p1) v1 = __ldcs(&x4[i1]);
    if (p2) v2 = __ldcs(&x4[i2]);
    if (p3) v3 = __ldcs(&x4[i3]);

    cudaGridDependencySynchronize();   // wait for reduce grid to finish

    const float t = g_total;
    if (p0) { v0.x += t; v0.y += t; v0.z += t; v0.w += t; __stcs(&o4[i0], v0); }
    if (p1) { v1.x += t; v1.y += t; v1.z += t; v1.w += t; __stcs(&o4[i1], v1); }
    if (p2) { v2.x += t; v2.y += t; v2.z += t; v2.w += t; __stcs(&o4[i2], v2); }
    if (p3) { v3.x += t; v3.y += t; v3.z += t; v3.w += t; __stcs(&o4[i3], v3); }
}

extern "C" void kernel_launch(void* const* d_in, const int* in_sizes, int n_in,
                              void* d_out, int out_size) {
    const float* x = (const float*)d_in[0];
    float* out = (float*)d_out;
    long long n = (long long)in_sizes[0];     // 67108864, divisible by 4
    long long n4 = n / 4;                     // 16777216 = 16384 * 1024

    reduce_kernel<<<RED_BLOCKS, NTHREADS>>>((const float4*)x, n4);

    long long add_blocks = (n4 + 4 * NTHREADS - 1) / (4 * NTHREADS);  // 16384

    cudaLaunchConfig_t cfg = {};
    cfg.gridDim = dim3((unsigned)add_blocks, 1, 1);
    cfg.blockDim = dim3(NTHREADS, 1, 1);
    cfg.dynamicSmemBytes = 0;
    cfg.stream = 0;
    cudaLaunchAttribute attr[1];
    attr[0].id = cudaLaunchAttributeProgrammaticStreamSerialization;
    attr[0].val.programmaticStreamSerializationAllowed = 1;
    cfg.attrs = attr;
    cfg.numAttrs = 1;
    cudaLaunchKernelEx(&cfg, add_kernel, (const float4*)x, (float4*)out, n4);
}

// round 14
// speedup vs baseline: 1.3684x; 1.3684x over previous
#include <cuda_runtime.h>
#include <cuda_bf16.h>

// out = x + total, total = n*(n-1)/2 if n>1 else 0, n = trunc(sum(x)),
// x: 8192x8192 fp32 (64M elems, 256MB).
//
// R13 post-mortem: tiny-CTA contiguous reduce was catastrophic (per-CTA
// fence+atomic tail amortized over 16KB). Reduce locked at the proven shape:
// 740 persistent CTAs (one wave @ clamp 5), MLP=4.
// R14 changes vs R11 (123.7 best):
//  - reduce: FORWARD walk + __ldcs streaming loads (backward L2-carryover
//    never showed a clean win; streaming avoids 256MB of L2 alloc churn).
//  - add: 8 float4/thread, all 8 loads issued BEFORE
//    cudaGridDependencySynchronize() -> deeper PDL overlap of the reduce tail.

#define NTHREADS 256
#define RED_BLOCKS 740      // 148 SMs * 5 CTAs — one exact wave

__device__ double g_partials[RED_BLOCKS];
__device__ float g_total;
__device__ unsigned int g_arrive;   // zero-init; finisher resets each launch

__global__ __launch_bounds__(NTHREADS, 5)
void reduce_kernel(const float4* __restrict__ x4, long long n4) {
    float a0 = 0.f, a1 = 0.f, a2 = 0.f, a3 = 0.f;
    const long long stride = (long long)RED_BLOCKS * NTHREADS;
    long long i = (long long)blockIdx.x * NTHREADS + threadIdx.x;

    // forward walk, 4 independent streaming loads in flight
    for (; i + 3 * stride < n4; i += 4 * stride) {
        float4 v0 = __ldcs(&x4[i]);
        float4 v1 = __ldcs(&x4[i + stride]);
        float4 v2 = __ldcs(&x4[i + 2 * stride]);
        float4 v3 = __ldcs(&x4[i + 3 * stride]);
        a0 += v0.x; a1 += v0.y; a2 += v0.z; a3 += v0.w;
        a0 += v1.x; a1 += v1.y; a2 += v1.z; a3 += v1.w;
        a0 += v2.x; a1 += v2.y; a2 += v2.z; a3 += v2.w;
        a0 += v3.x; a1 += v3.y; a2 += v3.z; a3 += v3.w;
    }
    for (; i < n4; i += stride) {
        float4 v = __ldcs(&x4[i]);
        a0 += v.x; a1 += v.y; a2 += v.z; a3 += v.w;
    }
    double acc = ((double)a0 + (double)a1) + ((double)a2 + (double)a3);

    __shared__ double s[NTHREADS];
    s[threadIdx.x] = acc;
    __syncthreads();
    #pragma unroll
    for (int off = NTHREADS / 2; off > 0; off >>= 1) {
        if (threadIdx.x < off) s[threadIdx.x] += s[threadIdx.x + off];
        __syncthreads();
    }

    __shared__ int is_last;
    if (threadIdx.x == 0) {
        g_partials[blockIdx.x] = s[0];
        __threadfence();                       // partial visible GPU-wide
        unsigned int prev = atomicAdd(&g_arrive, 1u);
        is_last = (prev == RED_BLOCKS - 1);
        if (is_last) atomicExch(&g_arrive, 0u);  // reset for next graph replay
    }
    __syncthreads();

    // Last-arriving CTA finalizes in a FIXED order -> deterministic result
    // regardless of which CTA is last.
    if (is_last) {
        double acc2 = 0.0;
        #pragma unroll
        for (int i2 = threadIdx.x; i2 < RED_BLOCKS; i2 += NTHREADS)
            acc2 += g_partials[i2];
        s[threadIdx.x] = acc2;
        __syncthreads();
        #pragma unroll
        for (int off = NTHREADS / 2; off > 0; off >>= 1) {
            if (threadIdx.x < off) s[threadIdx.x] += s[threadIdx.x + off];
            __syncthreads();
        }
        if (threadIdx.x == 0) {
            double total_sum = s[0];
            double nn = trunc(total_sum);   // int() truncates toward zero
            g_total = (float)((nn > 1.0) ? nn * (nn - 1.0) * 0.5 : 0.0);
        }
    }
}

// Non-persistent streaming add, 8 float4/thread, PDL-overlapped:
// all 8 loads issue before the grid-dependency sync (read-only, no hazard),
// g_total is read after it.
__global__ __launch_bounds__(NTHREADS)
void add_kernel(const float4* __restrict__ x4, float4* __restrict__ o4,
                long long n4) {
    const long long base = (long long)blockIdx.x * (8 * NTHREADS) + threadIdx.x;
    long long idx[8];
    float4 v[8];
    bool p[8];
    #pragma unroll
    for (int k = 0; k < 8; k++) {
        idx[k] = base + (long long)k * NTHREADS;
        p[k] = idx[k] < n4;
        if (p[k]) v[k] = __ldcs(&x4[idx[k]]);
    }

    cudaGridDependencySynchronize();   // wait for reduce grid to finish

    const float t = g_total;
    #pragma unroll
    for (int k = 0; k < 8; k++) {
        if (p[k]) {
            v[k].x += t; v[k].y += t; v[k].z += t; v[k].w += t;
            __stcs(&o4[idx[k]], v[k]);
        }
    }
}

extern "C" void kernel_launch(void* const* d_in, const int* in_sizes, int n_in,
                              void* d_out, int out_size) {
    const float* x = (const float*)d_in[0];
    float* out = (float*)d_out;
    long long n = (long long)in_sizes[0];     // 67108864, divisible by 4
    long long n4 = n / 4;                     // 16777216

    reduce_kernel<<<RED_BLOCKS, NTHREADS>>>((const float4*)x, n4);

    long long add_blocks = (n4 + 8 * NTHREADS - 1) / (8 * NTHREADS);  // 8192

    cudaLaunchConfig_t cfg = {};
    cfg.gridDim = dim3((unsigned)add_blocks, 1, 1);
    cfg.blockDim = dim3(NTHREADS, 1, 1);
    cfg.dynamicSmemBytes = 0;
    cfg.stream = 0;
    cudaLaunchAttribute attr[1];
    attr[0].id = cudaLaunchAttributeProgrammaticStreamSerialization;
    attr[0].val.programmaticStreamSerializationAllowed = 1;
    cfg.attrs = attr;
    cfg.numAttrs = 1;
    cudaLaunchKernelEx(&cfg, add_kernel, (const float4*)x, (float4*)out, n4);
}

// round 15
// speedup vs baseline: 1.4441x; 1.0554x over previous
#include <cuda_runtime.h>
#include <cuda_bf16.h>

// out = x + total, total = n*(n-1)/2 if n>1 else 0, n = trunc(sum(x)),
// x: 8192x8192 fp32 (64M elems, 256MB).
//
// R14 post-mortem: forward+__ldcs reduce cost ~8us (the backward default-
// policy walk's L2 residue feeds the PDL-overlapped add prelude). Clean
// recombination of the two measured bests:
//  - reduce: R11 exact (740 CTAs @ clamp 5, MLP=4, BACKWARD walk, default
//    loads, last-block fused deterministic finalize).
//  - add: R14 exact (8 float4/thread, __ldcs prelude before the PDL sync,
//    __stcs stores) — 73.95us @ 6.51 TB/s measured.

#define NTHREADS 256
#define RED_BLOCKS 740      // 148 SMs * 5 CTAs — one exact wave

__device__ double g_partials[RED_BLOCKS];
__device__ float g_total;
__device__ unsigned int g_arrive;   // zero-init; finisher resets each launch

__global__ __launch_bounds__(NTHREADS, 5)
void reduce_kernel(const float4* __restrict__ x4, long long n4) {
    float a0 = 0.f, a1 = 0.f, a2 = 0.f, a3 = 0.f;
    const long long stride = (long long)RED_BLOCKS * NTHREADS;
    const long long tid = (long long)blockIdx.x * NTHREADS + threadIdx.x;
    const long long niter = (n4 + stride - 1) / stride;

    long long j = niter - 1;
    // top (possibly partial) chunk; walk BACKWARD so L2 ends holding x's front
    {
        long long i = j * stride + tid;
        if (i < n4) {
            float4 v = x4[i];
            a0 += v.x; a1 += v.y; a2 += v.z; a3 += v.w;
        }
        j--;
    }
    for (; j >= 3; j -= 4) {
        float4 v0 = x4[(j    ) * stride + tid];
        float4 v1 = x4[(j - 1) * stride + tid];
        float4 v2 = x4[(j - 2) * stride + tid];
        float4 v3 = x4[(j - 3) * stride + tid];
        a0 += v0.x; a1 += v0.y; a2 += v0.z; a3 += v0.w;
        a0 += v1.x; a1 += v1.y; a2 += v1.z; a3 += v1.w;
        a0 += v2.x; a1 += v2.y; a2 += v2.z; a3 += v2.w;
        a0 += v3.x; a1 += v3.y; a2 += v3.z; a3 += v3.w;
    }
    for (; j >= 0; j--) {
        float4 v = x4[j * stride + tid];
        a0 += v.x; a1 += v.y; a2 += v.z; a3 += v.w;
    }
    double acc = ((double)a0 + (double)a1) + ((double)a2 + (double)a3);

    __shared__ double s[NTHREADS];
    s[threadIdx.x] = acc;
    __syncthreads();
    #pragma unroll
    for (int off = NTHREADS / 2; off > 0; off >>= 1) {
        if (threadIdx.x < off) s[threadIdx.x] += s[threadIdx.x + off];
        __syncthreads();
    }

    __shared__ int is_last;
    if (threadIdx.x == 0) {
        g_partials[blockIdx.x] = s[0];
        __threadfence();                       // partial visible GPU-wide
        unsigned int prev = atomicAdd(&g_arrive, 1u);
        is_last = (prev == RED_BLOCKS - 1);
        if (is_last) atomicExch(&g_arrive, 0u);  // reset for next graph replay
    }
    __syncthreads();

    // Last-arriving CTA finalizes in a FIXED order -> deterministic result
    // regardless of which CTA is last.
    if (is_last) {
        double acc2 = 0.0;
        #pragma unroll
        for (int i2 = threadIdx.x; i2 < RED_BLOCKS; i2 += NTHREADS)
            acc2 += g_partials[i2];
        s[threadIdx.x] = acc2;
        __syncthreads();
        #pragma unroll
        for (int off = NTHREADS / 2; off > 0; off >>= 1) {
            if (threadIdx.x < off) s[threadIdx.x] += s[threadIdx.x + off];
            __syncthreads();
        }
        if (threadIdx.x == 0) {
            double total_sum = s[0];
            double nn = trunc(total_sum);   // int() truncates toward zero
            g_total = (float)((nn > 1.0) ? nn * (nn - 1.0) * 0.5 : 0.0);
        }
    }
}

// Non-persistent streaming add, 8 float4/thread, PDL-overlapped:
// all 8 loads issue before the grid-dependency sync (read-only, no hazard),
// g_total is read after it.
__global__ __launch_bounds__(NTHREADS)
void add_kernel(const float4* __restrict__ x4, float4* __restrict__ o4,
                long long n4) {
    const long long base = (long long)blockIdx.x * (8 * NTHREADS) + threadIdx.x;
    long long idx[8];
    float4 v[8];
    bool p[8];
    #pragma unroll
    for (int k = 0; k < 8; k++) {
        idx[k] = base + (long long)k * NTHREADS;
        p[k] = idx[k] < n4;
        if (p[k]) v[k] = __ldcs(&x4[idx[k]]);
    }

    cudaGridDependencySynchronize();   // wait for reduce grid to finish

    const float t = g_total;
    #pragma unroll
    for (int k = 0; k < 8; k++) {
        if (p[k]) {
            v[k].x += t; v[k].y += t; v[k].z += t; v[k].w += t;
            __stcs(&o4[idx[k]], v[k]);
        }
    }
}

extern "C" void kernel_launch(void* const* d_in, const int* in_sizes, int n_in,
                              void* d_out, int out_size) {
    const float* x = (const float*)d_in[0];
    float* out = (float*)d_out;
    long long n = (long long)in_sizes[0];     // 67108864, divisible by 4
    long long n4 = n / 4;                     // 16777216

    reduce_kernel<<<RED_BLOCKS, NTHREADS>>>((const float4*)x, n4);

    long long add_blocks = (n4 + 8 * NTHREADS - 1) / (8 * NTHREADS);  // 8192

    cudaLaunchConfig_t cfg = {};
    cfg.gridDim = dim3((unsigned)add_blocks, 1, 1);
    cfg.blockDim = dim3(NTHREADS, 1, 1);
    cfg.dynamicSmemBytes = 0;
    cfg.stream = 0;
    cudaLaunchAttribute attr[1];
    attr[0].id = cudaLaunchAttributeProgrammaticStreamSerialization;
    attr[0].val.programmaticStreamSerializationAllowed = 1;
    cfg.attrs = attr;
    cfg.numAttrs = 1;
    cudaLaunchKernelEx(&cfg, add_kernel, (const float4*)x, (float4*)out, n4);
}

// round 16
// speedup vs baseline: 1.4550x; 1.0075x over previous
#include <cuda_runtime.h>
#include <cuda_bf16.h>

// out = x + total, total = n*(n-1)/2 if n>1 else 0, n = trunc(sum(x)),
// x: 8192x8192 fp32 (64M elems, 256MB).
//
// R15 post-mortem: add-8 is high-variance (occ 50%); add-4 is stable at
// ~74.5 (occ 80%). Reduce side hit 47.3 best. This round:
//  - add: R11-exact 4 float4/thread PDL add.
//  - reduce: R11 shape (740 @ clamp 5, backward, default loads) with the ONLY
//    change MLP 4 -> 6 (clean unconfounded test; fits 51-reg budget).

#define NTHREADS 256
#define RED_BLOCKS 740      // 148 SMs * 5 CTAs — one exact wave

__device__ double g_partials[RED_BLOCKS];
__device__ float g_total;
__device__ unsigned int g_arrive;   // zero-init; finisher resets each launch

__global__ __launch_bounds__(NTHREADS, 5)
void reduce_kernel(const float4* __restrict__ x4, long long n4) {
    float a0 = 0.f, a1 = 0.f, a2 = 0.f, a3 = 0.f;
    const long long stride = (long long)RED_BLOCKS * NTHREADS;
    const long long tid = (long long)blockIdx.x * NTHREADS + threadIdx.x;
    const long long niter = (n4 + stride - 1) / stride;

    long long j = niter - 1;
    // top (possibly partial) chunk; walk BACKWARD so L2 ends holding x's front
    {
        long long i = j * stride + tid;
        if (i < n4) {
            float4 v = x4[i];
            a0 += v.x; a1 += v.y; a2 += v.z; a3 += v.w;
        }
        j--;
    }
    // MLP=6 main loop: 6 independent loads in flight
    for (; j >= 5; j -= 6) {
        float4 v0 = x4[(j    ) * stride + tid];
        float4 v1 = x4[(j - 1) * stride + tid];
        float4 v2 = x4[(j - 2) * stride + tid];
        float4 v3 = x4[(j - 3) * stride + tid];
        float4 v4 = x4[(j - 4) * stride + tid];
        float4 v5 = x4[(j - 5) * stride + tid];
        a0 += v0.x; a1 += v0.y; a2 += v0.z; a3 += v0.w;
        a0 += v1.x; a1 += v1.y; a2 += v1.z; a3 += v1.w;
        a0 += v2.x; a1 += v2.y; a2 += v2.z; a3 += v2.w;
        a0 += v3.x; a1 += v3.y; a2 += v3.z; a3 += v3.w;
        a0 += v4.x; a1 += v4.y; a2 += v4.z; a3 += v4.w;
        a0 += v5.x; a1 += v5.y; a2 += v5.z; a3 += v5.w;
    }
    for (; j >= 0; j--) {
        float4 v = x4[j * stride + tid];
        a0 += v.x; a1 += v.y; a2 += v.z; a3 += v.w;
    }
    double acc = ((double)a0 + (double)a1) + ((double)a2 + (double)a3);

    __shared__ double s[NTHREADS];
    s[threadIdx.x] = acc;
    __syncthreads();
    #pragma unroll
    for (int off = NTHREADS / 2; off > 0; off >>= 1) {
        if (threadIdx.x < off) s[threadIdx.x] += s[threadIdx.x + off];
        __syncthreads();
    }

    __shared__ int is_last;
    if (threadIdx.x == 0) {
        g_partials[blockIdx.x] = s[0];
        __threadfence();                       // partial visible GPU-wide
        unsigned int prev = atomicAdd(&g_arrive, 1u);
        is_last = (prev == RED_BLOCKS - 1);
        if (is_last) atomicExch(&g_arrive, 0u);  // reset for next graph replay
    }
    __syncthreads();

    // Last-arriving CTA finalizes in a FIXED order -> deterministic result
    // regardless of which CTA is last.
    if (is_last) {
        double acc2 = 0.0;
        #pragma unroll
        for (int i2 = threadIdx.x; i2 < RED_BLOCKS; i2 += NTHREADS)
            acc2 += g_partials[i2];
        s[threadIdx.x] = acc2;
        __syncthreads();
        #pragma unroll
        for (int off = NTHREADS / 2; off > 0; off >>= 1) {
            if (threadIdx.x < off) s[threadIdx.x] += s[threadIdx.x + off];
            __syncthreads();
        }
        if (threadIdx.x == 0) {
            double total_sum = s[0];
            double nn = trunc(total_sum);   // int() truncates toward zero
            g_total = (float)((nn > 1.0) ? nn * (nn - 1.0) * 0.5 : 0.0);
        }
    }
}

// Non-persistent streaming add, 4 float4/thread, PDL-overlapped:
// all loads issue before the grid-dependency sync (read-only, no hazard),
// g_total is read after it.
__global__ __launch_bounds__(NTHREADS)
void add_kernel(const float4* __restrict__ x4, float4* __restrict__ o4,
                long long n4) {
    const long long base = (long long)blockIdx.x * (4 * NTHREADS) + threadIdx.x;
    const long long i0 = base;
    const long long i1 = base + NTHREADS;
    const long long i2 = base + 2 * NTHREADS;
    const long long i3 = base + 3 * NTHREADS;

    float4 v0, v1, v2, v3;
    bool p0 = i0 < n4, p1 = i1 < n4, p2 = i2 < n4, p3 = i3 < n4;
    if (p0) v0 = __ldcs(&x4[i0]);
    if (p1) v1 = __ldcs(&x4[i1]);
    if (p2) v2 = __ldcs(&x4[i2]);
    if (p3) v3 = __ldcs(&x4[i3]);

    cudaGridDependencySynchronize();   // wait for reduce grid to finish

    const float t = g_total;
    if (p0) { v0.x += t; v0.y += t; v0.z += t; v0.w += t; __stcs(&o4[i0], v0); }
    if (p1) { v1.x += t; v1.y += t; v1.z += t; v1.w += t; __stcs(&o4[i1], v1); }
    if (p2) { v2.x += t; v2.y += t; v2.z += t; v2.w += t; __stcs(&o4[i2], v2); }
    if (p3) { v3.x += t; v3.y += t; v3.z += t; v3.w += t; __stcs(&o4[i3], v3); }
}

extern "C" void kernel_launch(void* const* d_in, const int* in_sizes, int n_in,
                              void* d_out, int out_size) {
    const float* x = (const float*)d_in[0];
    float* out = (float*)d_out;
    long long n = (long long)in_sizes[0];     // 67108864, divisible by 4
    long long n4 = n / 4;                     // 16777216

    reduce_kernel<<<RED_BLOCKS, NTHREADS>>>((const float4*)x, n4);

    long long add_blocks = (n4 + 4 * NTHREADS - 1) / (4 * NTHREADS);  // 16384

    cudaLaunchConfig_t cfg = {};
    cfg.gridDim = dim3((unsigned)add_blocks, 1, 1);
    cfg.blockDim = dim3(NTHREADS, 1, 1);
    cfg.dynamicSmemBytes = 0;
    cfg.stream = 0;
    cudaLaunchAttribute attr[1];
    attr[0].id = cudaLaunchAttributeProgrammaticStreamSerialization;
    attr[0].val.programmaticStreamSerializationAllowed = 1;
    cfg.attrs = attr;
    cfg.numAttrs = 1;
    cudaLaunchKernelEx(&cfg, add_kernel, (const float4*)x, (float4*)out, n4);
}